// round 16
// baseline (speedup 1.0000x reference)
#include <cuda_runtime.h>
#include <cuda_bf16.h>

#define THREADS 256
#define NWARP   8
#define CAP     2048     // candidate cap per row
#define WBINS   4096     // window-kernel bins: positive float bits [30:19]
#define SROWS   2        // sample rows for the window
#define MARGIN  120      // covers per-row binomial spread + sampling error + bin width

// Scratch (n <= 16384 supported; actual n = 4096)
__device__ float g_bf[16384];
__device__ float g_win[2];   // [0] = T_lo, [1] = T_hi  (+inf => force fallback)

__global__ void boost_kernel(const float* __restrict__ duty,
                             const int* __restrict__ kp, int n) {
    int i = blockIdx.x * blockDim.x + threadIdx.x;
    if (i < n) {
        float td = (float)(*kp) / (float)n;
        g_bf[i] = expf(td - duty[i]);   // boostStrength = 1.0
    }
}

// Monotone float -> uint key (fallback path only)
__device__ __forceinline__ unsigned f2key(float f) {
    unsigned u = __float_as_uint(f);
    return u ^ (unsigned)(((int)u >> 31) | 0x80000000);
}
__device__ __forceinline__ float key2f(unsigned k) {
    unsigned m = ((int)k < 0) ? 0x80000000u : 0xFFFFFFFFu;
    return __uint_as_float(k ^ m);
}

// One CTA: histogram SROWS sample rows of boosted positives at 13-bit
// granularity, pick global cutoffs so that for (almost) every row
// #{b >= T_hi} < k <= #{b >= T_lo}. Defaults +inf force the exact fallback.
__global__ void window_kernel(const float* __restrict__ x,
                              const int* __restrict__ kp, int n) {
    __shared__ unsigned hist[WBINS];
    __shared__ unsigned wtot[NWARP];
    const int t = threadIdx.x, lane = t & 31, wid = t >> 5;

    if (t == 0) {
        g_win[0] = __int_as_float(0x7F800000);   // +inf
        g_win[1] = __int_as_float(0x7F800000);
    }
    for (int i = t; i < WBINS; i += THREADS) hist[i] = 0;
    __syncthreads();

    for (int r = 0; r < SROWS; r++) {
        const float* xr = x + (size_t)r * n;
        for (int i = t; i < n; i += THREADS) {
            float bv = xr[i] * g_bf[i];
            unsigned u = __float_as_uint(bv);
            if ((int)u >= 0) atomicAdd(&hist[u >> 19], 1u);
        }
    }
    __syncthreads();

    const unsigned k0  = (unsigned)*kp;
    const unsigned thi = (k0 > MARGIN ? k0 - MARGIN : 0u) * SROWS;
    const unsigned tlo = (k0 + MARGIN) * SROWS;

    // Suffix-count scan; thread t owns bins [16t, 16t+16)
    const int BPT = WBINS / THREADS;  // 16
    unsigned base = (unsigned)t * BPT;
    unsigned hh[16];
    unsigned tot = 0;
    const uint4* hv = (const uint4*)(hist + base);
    #pragma unroll
    for (int q = 0; q < 4; q++) {
        uint4 h4 = hv[q];
        hh[q*4+0] = h4.x; hh[q*4+1] = h4.y; hh[q*4+2] = h4.z; hh[q*4+3] = h4.w;
        tot += h4.x + h4.y + h4.z + h4.w;
    }
    unsigned v = tot;
    #pragma unroll
    for (int off = 1; off < 32; off <<= 1) {
        unsigned u = __shfl_down_sync(0xFFFFFFFFu, v, off);
        if (lane + off < 32) v += u;
    }
    if (lane == 0) wtot[wid] = v;
    __syncthreads();
    unsigned run = v - tot;
    for (int j = wid + 1; j < NWARP; j++) run += wtot[j];

    #pragma unroll
    for (int i = BPT - 1; i >= 0; i--) {
        unsigned nxt = run;      // suffix(bin+1)
        run += hh[i];            // suffix(bin)
        unsigned bi = base + (unsigned)i;
        if (run > thi && nxt <= thi)
            g_win[1] = __uint_as_float((bi + 1u) << 19);   // T_hi
        if (run > tlo && nxt <= tlo)
            g_win[0] = __uint_as_float((bi + 1u) << 19);   // T_lo
    }
}

template <int EPV>  // float4 elements per thread per row
__global__ __launch_bounds__(THREADS, 4)
void kwinner_kernel(const float* __restrict__ x,
                    const int* __restrict__ kp,
                    float* __restrict__ out, int n) {
    const int row  = blockIdx.x;
    const int t    = threadIdx.x;
    const int lane = t & 31;
    const int wid  = t >> 5;
    constexpr int NK = EPV * 4;

    __shared__ unsigned list[CAP];
    __shared__ unsigned wtot[NWARP];
    __shared__ unsigned sNum, sMin;

    if (t == 0) { sNum = 0; sMin = 0xFFFFFFFFu; }

    const float T_lo = g_win[0];
    const float T_hi = g_win[1];

    const float4* xrow = (const float4*)(x + (size_t)row * n);
    const float4* bfv  = (const float4*)g_bf;

    float4 xv[EPV];     // x in registers (R12 operating point: 64 regs, occ 4)
    float  b[NK];
    #pragma unroll
    for (int j = 0; j < EPV; j++) {
        int f = t + j * THREADS;
        xv[j] = xrow[f];
        float4 bf = bfv[f];
        b[j*4+0] = xv[j].x * bf.x;
        b[j*4+1] = xv[j].y * bf.y;
        b[j*4+2] = xv[j].z * bf.z;
        b[j*4+3] = xv[j].w * bf.w;
    }
    __syncthreads();   // sNum/sMin init visible

    // No histogram: one compare per element + rare candidate compaction.
    unsigned cnt = 0;
    #pragma unroll
    for (int e = 0; e < NK; e++) {
        float bv = b[e];
        if (bv >= T_hi) {
            cnt++;
        } else if (bv >= T_lo) {   // candidate window [T_lo, T_hi)
            unsigned p = atomicAdd(&sNum, 1u);
            if (p < CAP) list[p] = __float_as_uint(bv);  // positive bits: uint order == float order
        }
    }
    cnt = __reduce_add_sync(0xFFFFFFFFu, cnt);
    if (lane == 0) wtot[wid] = cnt;
    __syncthreads();

    unsigned bsum = 0;
    #pragma unroll
    for (int j = 0; j < NWARP; j++) bsum += wtot[j];
    const unsigned C  = sNum;
    const unsigned k0 = (unsigned)__ldg(kp);

    const bool valid = (bsum < k0) && (bsum + C >= k0) && (C <= CAP);

    float thresh;
    if (valid) {
        const unsigned kr = k0 - bsum;   // rank of answer within candidates
        // Min-trick rank: the kr-th largest candidate = min{ci : gt(ci) < kr}.
        unsigned best = 0xFFFFFFFFu;
        for (unsigned i = (unsigned)t; i < C; i += THREADS) {
            unsigned ki = list[i];
            unsigned gt = 0;
            #pragma unroll 4
            for (unsigned j = 0; j < C; j++)
                gt += (list[j] > ki) ? 1u : 0u;
            if (gt < kr && ki < best) best = ki;
        }
        best = __reduce_min_sync(0xFFFFFFFFu, best);
        if (lane == 0) atomicMin(&sMin, best);
        __syncthreads();
        thresh = __uint_as_float(sMin);
    } else {
        // Exactness fallback (window miss / degenerate data): block-wide
        // greedy bit-descent over full monotone keys. Rare.
        unsigned thr = 0;
        for (int bb = 31; bb >= 0; bb--) {
            unsigned test = thr | (1u << bb);
            unsigned c = 0;
            #pragma unroll
            for (int e = 0; e < NK; e++) c += (f2key(b[e]) >= test) ? 1u : 0u;
            c = __reduce_add_sync(0xFFFFFFFFu, c);
            if (lane == 0) wtot[wid] = c;
            __syncthreads();
            unsigned cb = 0;
            #pragma unroll
            for (int j = 0; j < NWARP; j++) cb += wtot[j];
            if (cb >= k0) thr = test;
            __syncthreads();
        }
        thresh = key2f(thr);
    }

    // Output: EXACT passthrough of register-resident x; float >= mask
    // (identical semantics to the reference's boosted >= bottom).
    float4* orow = (float4*)(out + (size_t)row * n);
    #pragma unroll
    for (int j = 0; j < EPV; j++) {
        int f = t + j * THREADS;
        float4 o;
        o.x = (b[j*4+0] >= thresh) ? xv[j].x : 0.0f;
        o.y = (b[j*4+1] >= thresh) ? xv[j].y : 0.0f;
        o.z = (b[j*4+2] >= thresh) ? xv[j].z : 0.0f;
        o.w = (b[j*4+3] >= thresh) ? xv[j].w : 0.0f;
        orow[f] = o;
    }
}

extern "C" void kernel_launch(void* const* d_in, const int* in_sizes, int n_in,
                              void* d_out, int out_size) {
    const float* x    = (const float*)d_in[0];
    const float* duty = (const float*)d_in[1];
    const int*   kp   = (const int*)d_in[2];
    float*       out  = (float*)d_out;

    int n    = in_sizes[1];          // 4096
    int rows = in_sizes[0] / n;      // 8192

    boost_kernel<<<(n + 255) / 256, 256>>>(duty, kp, n);
    window_kernel<<<1, THREADS>>>(x, kp, n);

    int epv = n / (THREADS * 4);
    switch (epv) {
        case 1:  kwinner_kernel<1><<<rows, THREADS>>>(x, kp, out, n);  break;
        case 2:  kwinner_kernel<2><<<rows, THREADS>>>(x, kp, out, n);  break;
        case 4:  kwinner_kernel<4><<<rows, THREADS>>>(x, kp, out, n);  break;
        case 8:  kwinner_kernel<8><<<rows, THREADS>>>(x, kp, out, n);  break;
        case 16: kwinner_kernel<16><<<rows, THREADS>>>(x, kp, out, n); break;
        default: break; // unsupported shape (not expected for this problem)
    }
}